// round 12
// baseline (speedup 1.0000x reference)
#include <cuda_runtime.h>
#include <cuda_bf16.h>
#include <math.h>
#include <stdint.h>

// ---------------------------------------------------------------------------
// NgramRF GNN — R10 GEMM (natural regs, cp.async pipeline, padded K) +
// ticket-fused BN finalize (no k_finalize launches) + grid-stride pad.
// ---------------------------------------------------------------------------

#define N_NODES  100000
#define N_EDGES  1600000
#define N_GRAPHS 4096
#define IN_FEAT  74
#define PADK     96
#define HIDDEN   128
#define OUT_FEAT 128
#define N_CONV   3
#define NGRAM    6
#define BN_EPS   1e-5f

typedef unsigned long long u64;

// ------------------------- device scratch (static) -------------------------
__device__ float g_x[N_NODES * HIDDEN];     // pre-BN node features
__device__ float g_m[N_NODES * HIDDEN];     // aggregated messages
__device__ float g_featp[N_NODES * PADK];   // padded features
__device__ float g_Winp[PADK * HIDDEN];     // padded W_in
__device__ int   g_deg[N_NODES];
__device__ int   g_rowptr[N_NODES + 1];
__device__ int   g_cursor[N_NODES];
__device__ int   g_col[N_EDGES];
__device__ int   g_gdeg[N_GRAPHS];
__device__ int   g_growptr[N_GRAPHS + 1];
__device__ float g_combined[N_GRAPHS * HIDDEN];
__device__ float g_sum[HIDDEN];
__device__ float g_sumsq[HIDDEN];
__device__ float g_scale[HIDDEN];
__device__ float g_shift[HIDDEN];
__device__ float g_w[NGRAM];
__device__ unsigned int g_ticket;

// ------------------------------ helpers -------------------------------------
__device__ __forceinline__ u64 fma2(u64 a, u64 b, u64 c) {
    u64 d;
    asm("fma.rn.f32x2 %0, %1, %2, %3;" : "=l"(d) : "l"(a), "l"(b), "l"(c));
    return d;
}
__device__ __forceinline__ u64 dup2(float x) {
    u64 d;
    asm("mov.b64 %0, {%1, %1};" : "=l"(d) : "f"(x));
    return d;
}
__device__ __forceinline__ void unpack2(u64 v, float& lo, float& hi) {
    asm("mov.b64 {%0, %1}, %2;" : "=f"(lo), "=f"(hi) : "l"(v));
}
__device__ __forceinline__ uint32_t smem_u32(const void* p) {
    uint32_t a;
    asm("{ .reg .u64 t; cvta.to.shared.u64 t, %1; cvt.u32.u64 %0, t; }" : "=r"(a) : "l"(p));
    return a;
}
__device__ __forceinline__ void cp16(uint32_t dst, const void* src, int src_bytes) {
    asm volatile("cp.async.cg.shared.global [%0], [%1], 16, %2;"
                 :: "r"(dst), "l"(src), "r"(src_bytes));
}
#define CP_COMMIT()  asm volatile("cp.async.commit_group;" ::: "memory")
#define CP_WAIT(N)   asm volatile("cp.async.wait_group %0;" :: "n"(N) : "memory")

// ------------------------------ tiny kernels -------------------------------
__global__ void k_softmax(const float* __restrict__ ngw) {
    if (threadIdx.x == 0) {
        float mx = -1e30f;
        for (int i = 0; i < NGRAM; i++) mx = fmaxf(mx, ngw[i]);
        float e[NGRAM], s = 0.f;
        for (int i = 0; i < NGRAM; i++) { e[i] = expf(ngw[i] - mx); s += e[i]; }
        for (int i = 0; i < NGRAM; i++) g_w[i] = e[i] / s;
    }
}

// grid-stride pad: features [N,74]->[N,96] and W_in [74,128]->[96,128]
__global__ void __launch_bounds__(256)
k_pad(const float* __restrict__ f, const float* __restrict__ Win) {
    int i  = blockIdx.x * blockDim.x + threadIdx.x;
    int st = gridDim.x * blockDim.x;
    const int totF = N_NODES * PADK;
    for (int j = i; j < totF; j += st) {
        int r = j / PADK;
        int c = j - r * PADK;
        g_featp[j] = (c < IN_FEAT) ? f[(size_t)r * IN_FEAT + c] : 0.f;
    }
    const int totW = PADK * HIDDEN;
    for (int j = i; j < totW; j += st) {
        int w = j >> 7;
        g_Winp[j] = (w < IN_FEAT) ? Win[j] : 0.f;
    }
}

__global__ void k_hist(const int* __restrict__ dst) {
    int i  = blockIdx.x * blockDim.x + threadIdx.x;
    int st = gridDim.x * blockDim.x;
    for (int e = i; e < N_EDGES; e += st) atomicAdd(&g_deg[dst[e]], 1);
}

__global__ void k_ghist(const int* __restrict__ gid) {
    int i  = blockIdx.x * blockDim.x + threadIdx.x;
    int st = gridDim.x * blockDim.x;
    for (int v = i; v < N_NODES; v += st) atomicAdd(&g_gdeg[gid[v]], 1);
}

__global__ void k_scan(const int* __restrict__ deg, int* __restrict__ rowptr,
                       int* __restrict__ cursor, int n) {
    __shared__ int ssum[1024];
    const int T = 1024;
    int t   = threadIdx.x;
    int per = (n + T - 1) / T;
    int lo  = t * per;
    int hi  = min(lo + per, n);
    int s = 0;
    for (int i = lo; i < hi; i++) s += deg[i];
    ssum[t] = s;
    __syncthreads();
    for (int off = 1; off < T; off <<= 1) {
        int v = (t >= off) ? ssum[t - off] : 0;
        __syncthreads();
        ssum[t] += v;
        __syncthreads();
    }
    int run = ssum[t] - s;
    for (int i = lo; i < hi; i++) {
        rowptr[i] = run;
        if (cursor) cursor[i] = run;
        run += deg[i];
    }
    if (t == T - 1) rowptr[n] = ssum[T - 1];
}

__global__ void k_fill(const int* __restrict__ src, const int* __restrict__ dst) {
    int i  = blockIdx.x * blockDim.x + threadIdx.x;
    int st = gridDim.x * blockDim.x;
    for (int e = i; e < N_EDGES; e += st) {
        int p = atomicAdd(&g_cursor[dst[e]], 1);
        g_col[p] = src[e];
    }
}

// ----------------- SpMM: warp per row (verbatim R10) -------------------------
__global__ void __launch_bounds__(256)
k_spmm(const float4* __restrict__ x4, float4* __restrict__ m4, int apply_bn) {
    int wid  = (blockIdx.x * blockDim.x + threadIdx.x) >> 5;
    int lane = threadIdx.x & 31;
    if (wid >= N_NODES) return;
    int e = __ldg(g_rowptr + wid), end = __ldg(g_rowptr + wid + 1);
    float4 a = make_float4(0.f, 0.f, 0.f, 0.f);
    if (apply_bn) {
        float4 sc = ((const float4*)g_scale)[lane];
        float4 sh = ((const float4*)g_shift)[lane];
        for (; e + 2 <= end; e += 2) {
            int s0 = __ldg(g_col + e + 0);
            int s1 = __ldg(g_col + e + 1);
            float4 v0 = __ldg(x4 + (size_t)s0 * 32 + lane);
            float4 v1 = __ldg(x4 + (size_t)s1 * 32 + lane);
            a.x += fmaxf(fmaf(v0.x, sc.x, sh.x), 0.f) + fmaxf(fmaf(v1.x, sc.x, sh.x), 0.f);
            a.y += fmaxf(fmaf(v0.y, sc.y, sh.y), 0.f) + fmaxf(fmaf(v1.y, sc.y, sh.y), 0.f);
            a.z += fmaxf(fmaf(v0.z, sc.z, sh.z), 0.f) + fmaxf(fmaf(v1.z, sc.z, sh.z), 0.f);
            a.w += fmaxf(fmaf(v0.w, sc.w, sh.w), 0.f) + fmaxf(fmaf(v1.w, sc.w, sh.w), 0.f);
        }
        for (; e < end; e++) {
            int s = __ldg(g_col + e);
            float4 v = __ldg(x4 + (size_t)s * 32 + lane);
            a.x += fmaxf(fmaf(v.x, sc.x, sh.x), 0.f);
            a.y += fmaxf(fmaf(v.y, sc.y, sh.y), 0.f);
            a.z += fmaxf(fmaf(v.z, sc.z, sh.z), 0.f);
            a.w += fmaxf(fmaf(v.w, sc.w, sh.w), 0.f);
        }
    } else {
        for (; e + 4 <= end; e += 4) {
            int s0 = __ldg(g_col + e + 0);
            int s1 = __ldg(g_col + e + 1);
            int s2 = __ldg(g_col + e + 2);
            int s3 = __ldg(g_col + e + 3);
            float4 v0 = __ldg(x4 + (size_t)s0 * 32 + lane);
            float4 v1 = __ldg(x4 + (size_t)s1 * 32 + lane);
            float4 v2 = __ldg(x4 + (size_t)s2 * 32 + lane);
            float4 v3 = __ldg(x4 + (size_t)s3 * 32 + lane);
            a.x += (v0.x + v1.x) + (v2.x + v3.x);
            a.y += (v0.y + v1.y) + (v2.y + v3.y);
            a.z += (v0.z + v1.z) + (v2.z + v3.z);
            a.w += (v0.w + v1.w) + (v2.w + v3.w);
        }
        for (; e < end; e++) {
            int s = __ldg(g_col + e);
            float4 v = __ldg(x4 + (size_t)s * 32 + lane);
            a.x += v.x; a.y += v.y; a.z += v.z; a.w += v.w;
        }
    }
    m4[(size_t)wid * 32 + lane] = a;
}

// -- GEMM: C[n,128] = B[n,K] @ W[K,128], f32x2 8x8/thread, cp.async pipeline --
// Natural register allocation (no min-blocks cap). do_stats: fused BN stats +
// last-block finalize (scale/shift) via ticket.
#define BM 64
#define BN 128
#define BK 32
#define ASTR 36
#define GEMM_SMEM_FLOATS (2 * BM * ASTR + 2 * BK * BN)
__global__ void __launch_bounds__(128)
k_gemm128(const float* __restrict__ B, const float* __restrict__ W,
          float* __restrict__ C, int nrows, int K, int do_stats,
          const float* __restrict__ gamma, const float* __restrict__ beta) {
    extern __shared__ float sm[];
    __shared__ float s_cs[BN], s_cq[BN];
    __shared__ int s_last;
    int tid = threadIdx.x;
    int ty  = tid >> 4;
    int tx  = tid & 15;
    int row0 = blockIdx.x * BM;

    uint32_t sA0 = smem_u32(sm);                       // [2][BM][ASTR]
    uint32_t sW0 = sA0 + 2 * BM * ASTR * 4;            // [2][BK][BN]
    const float* sA = sm;
    const float* sW = sm + 2 * BM * ASTR;

    const int nch = K / BK;

    auto issue = [&](int s, int b) {
#pragma unroll
        for (int q = 0; q < 4; q++) {
            int fi = tid + q * 128;
            int m  = fi >> 3;
            int k4 = fi & 7;
            int r  = row0 + m;
            int rc = min(r, nrows - 1);
            const float* src = B + (size_t)rc * K + s * BK + k4 * 4;
            int sb = (r < nrows) ? 16 : 0;
            cp16(sA0 + (((b * BM + m) * ASTR) + k4 * 4) * 4, src, sb);
        }
#pragma unroll
        for (int q = 0; q < 8; q++) {
            int fi = tid + q * 128;
            int kk = fi >> 5;
            int n4 = fi & 31;
            cp16(sW0 + (((b * BK + kk) * BN) + n4 * 4) * 4,
                 W + (size_t)(s * BK + kk) * BN + n4 * 4, 16);
        }
        CP_COMMIT();
    };

    u64 acc2[8][4];
#pragma unroll
    for (int i = 0; i < 8; i++)
#pragma unroll
        for (int j = 0; j < 4; j++) acc2[i][j] = 0ull;

    issue(0, 0);

    for (int s = 0; s < nch; s++) {
        int b = s & 1;
        if (s + 1 < nch) {
            issue(s + 1, b ^ 1);
            CP_WAIT(1);
        } else {
            CP_WAIT(0);
        }
        __syncthreads();
        const float* cA = sA + b * BM * ASTR;
        const float* cW = sW + b * BK * BN;
#pragma unroll
        for (int kk = 0; kk < BK; kk++) {
            const u64* pW = (const u64*)(cW + kk * BN + tx * 8);
            u64 w0 = pW[0], w1 = pW[1], w2 = pW[2], w3 = pW[3];
#pragma unroll
            for (int i = 0; i < 8; i++) {
                u64 a2 = dup2(cA[(ty * 8 + i) * ASTR + kk]);
                acc2[i][0] = fma2(a2, w0, acc2[i][0]);
                acc2[i][1] = fma2(a2, w1, acc2[i][1]);
                acc2[i][2] = fma2(a2, w2, acc2[i][2]);
                acc2[i][3] = fma2(a2, w3, acc2[i][3]);
            }
        }
        __syncthreads();
    }

    float a[8][8];
#pragma unroll
    for (int i = 0; i < 8; i++)
#pragma unroll
        for (int j = 0; j < 4; j++) unpack2(acc2[i][j], a[i][2 * j], a[i][2 * j + 1]);

    if (do_stats) {
        s_cs[tid] = 0.f;
        s_cq[tid] = 0.f;
    }
    __syncthreads();
    if (do_stats) {
#pragma unroll
        for (int j = 0; j < 8; j++) {
            float cs = 0.f, cq = 0.f;
#pragma unroll
            for (int i = 0; i < 8; i++) { float v = a[i][j]; cs += v; cq += v * v; }
            atomicAdd(&s_cs[tx * 8 + j], cs);
            atomicAdd(&s_cq[tx * 8 + j], cq);
        }
        __syncthreads();
        atomicAdd(&g_sum[tid],   s_cs[tid]);
        atomicAdd(&g_sumsq[tid], s_cq[tid]);
        __syncthreads();
        if (tid == 0) {
            __threadfence();
            unsigned int t = atomicAdd(&g_ticket, 1u);
            s_last = (t == (unsigned int)gridDim.x - 1u) ? 1 : 0;
        }
        __syncthreads();
        if (s_last) {
            __threadfence();
            float invN = 1.f / (float)N_NODES;
            float mean = g_sum[tid] * invN;
            float var  = g_sumsq[tid] * invN - mean * mean;
            float sc   = __ldg(gamma + tid) * rsqrtf(var + BN_EPS);
            g_scale[tid] = sc;
            g_shift[tid] = __ldg(beta + tid) - mean * sc;
            g_sum[tid]   = 0.f;
            g_sumsq[tid] = 0.f;
            if (tid == 0) g_ticket = 0u;
        }
    }

#pragma unroll
    for (int i = 0; i < 8; i++) {
        int r = row0 + ty * 8 + i;
        if (r < nrows) {
            float4* o = (float4*)(C + (size_t)r * BN + tx * 8);
            o[0] = make_float4(a[i][0], a[i][1], a[i][2], a[i][3]);
            o[1] = make_float4(a[i][4], a[i][5], a[i][6], a[i][7]);
        }
    }
}

// ---------------- pooling: warp per graph, fused BN+ReLU --------------------
__global__ void __launch_bounds__(256)
k_pool(const float4* __restrict__ x4, int n) {
    int g    = (blockIdx.x * blockDim.x + threadIdx.x) >> 5;
    int lane = threadIdx.x & 31;
    if (g >= N_GRAPHS) return;
    float4 sc = ((const float4*)g_scale)[lane];
    float4 sh = ((const float4*)g_shift)[lane];
    int v = g_growptr[g], end = g_growptr[g + 1];
    float4 a = make_float4(0.f, 0.f, 0.f, 0.f);
    for (; v < end; v++) {
        float4 t = __ldg(x4 + (size_t)v * 32 + lane);
        a.x += fmaxf(fmaf(t.x, sc.x, sh.x), 0.f);
        a.y += fmaxf(fmaf(t.y, sc.y, sh.y), 0.f);
        a.z += fmaxf(fmaf(t.z, sc.z, sh.z), 0.f);
        a.w += fmaxf(fmaf(t.w, sc.w, sh.w), 0.f);
    }
    float w = g_w[n];
    float4* cb = (float4*)g_combined;
    float4 c = cb[(size_t)g * 32 + lane];
    c.x += w * a.x; c.y += w * a.y; c.z += w * a.z; c.w += w * a.w;
    cb[(size_t)g * 32 + lane] = c;
}

// ---------------------- MLP head: block per graph ---------------------------
__global__ void __launch_bounds__(128)
k_mlp(const float* __restrict__ W1, const float* __restrict__ b1,
      const float* __restrict__ W2, const float* __restrict__ b2,
      float* __restrict__ out) {
    int g = blockIdx.x;
    int t = threadIdx.x;
    __shared__ float row[HIDDEN];
    __shared__ float red[128];
    row[t] = g_combined[(size_t)g * HIDDEN + t];
    __syncthreads();
    float acc = b1[t];
#pragma unroll 8
    for (int k = 0; k < HIDDEN; k++) acc = fmaf(row[k], W1[(size_t)k * OUT_FEAT + t], acc);
    acc = (acc > 0.f) ? acc : 0.01f * acc;
    red[t] = acc * W2[t];
    __syncthreads();
    for (int off = 64; off > 0; off >>= 1) {
        if (t < off) red[t] += red[t + off];
        __syncthreads();
    }
    if (t == 0) {
        float z = red[0] + b2[0];
        out[g] = 1.f / (1.f + expf(-z));
    }
}

// ------------------------------- launcher -----------------------------------
extern "C" void kernel_launch(void* const* d_in, const int* in_sizes, int n_in,
                              void* d_out, int out_size) {
    const float* features = (const float*)d_in[0];
    const float* W_in     = (const float*)d_in[1];
    const float* conv_w   = (const float*)d_in[2];
    const float* bn_gamma = (const float*)d_in[3];
    const float* bn_beta  = (const float*)d_in[4];
    const float* ngw      = (const float*)d_in[5];
    const float* W1       = (const float*)d_in[6];
    const float* b1       = (const float*)d_in[7];
    const float* W2       = (const float*)d_in[8];
    const float* b2       = (const float*)d_in[9];
    const int*   src      = (const int*)d_in[10];
    const int*   dst      = (const int*)d_in[11];
    const int*   gid      = (const int*)d_in[12];
    float* out = (float*)d_out;

    float *dg_x, *dg_m, *dg_featp, *dg_Winp, *dg_comb, *dg_sum, *dg_sumsq;
    int *dg_deg, *dg_rowptr, *dg_cursor, *dg_gdeg, *dg_growptr;
    unsigned int* dg_ticket;
    cudaGetSymbolAddress((void**)&dg_x, g_x);
    cudaGetSymbolAddress((void**)&dg_m, g_m);
    cudaGetSymbolAddress((void**)&dg_featp, g_featp);
    cudaGetSymbolAddress((void**)&dg_Winp, g_Winp);
    cudaGetSymbolAddress((void**)&dg_comb, g_combined);
    cudaGetSymbolAddress((void**)&dg_sum, g_sum);
    cudaGetSymbolAddress((void**)&dg_sumsq, g_sumsq);
    cudaGetSymbolAddress((void**)&dg_deg, g_deg);
    cudaGetSymbolAddress((void**)&dg_rowptr, g_rowptr);
    cudaGetSymbolAddress((void**)&dg_cursor, g_cursor);
    cudaGetSymbolAddress((void**)&dg_gdeg, g_gdeg);
    cudaGetSymbolAddress((void**)&dg_growptr, g_growptr);
    cudaGetSymbolAddress((void**)&dg_ticket, g_ticket);

    cudaFuncSetAttribute(k_gemm128, cudaFuncAttributeMaxDynamicSharedMemorySize,
                         GEMM_SMEM_FLOATS * sizeof(float));

    // zero scratch via memset nodes
    cudaMemsetAsync(dg_deg, 0, N_NODES * sizeof(int));
    cudaMemsetAsync(dg_gdeg, 0, N_GRAPHS * sizeof(int));
    cudaMemsetAsync(dg_comb, 0, N_GRAPHS * HIDDEN * sizeof(float));
    cudaMemsetAsync(dg_sum, 0, HIDDEN * sizeof(float));
    cudaMemsetAsync(dg_sumsq, 0, HIDDEN * sizeof(float));
    cudaMemsetAsync(dg_ticket, 0, sizeof(unsigned int));

    const int gemm_blocks = (N_NODES + BM - 1) / BM;
    const int spmm_blocks = (N_NODES * 32 + 255) / 256;
    const size_t gemm_smem = GEMM_SMEM_FLOATS * sizeof(float);

    // launch #4 (profiled) = pipelined GEMM (vec path, K=96), natural regs
    k_pad<<<2048, 256>>>(features, W_in);                                // 1
    k_hist<<<2048, 256>>>(dst);                                          // 2
    k_scan<<<1, 1024>>>(dg_deg, dg_rowptr, dg_cursor, N_NODES);          // 3
    k_gemm128<<<gemm_blocks, 128, gemm_smem>>>(dg_featp, dg_Winp, dg_x,  // 4
                                               N_NODES, PADK, 0,
                                               bn_gamma, bn_beta);
    k_fill<<<2048, 256>>>(src, dst);                                     // 5
    k_ghist<<<256, 256>>>(gid);
    k_scan<<<1, 1024>>>(dg_gdeg, dg_growptr, (int*)0, N_GRAPHS);
    k_softmax<<<1, 32>>>(ngw);

    for (int n = 0; n < NGRAM; n++) {
        for (int j = 0; j < N_CONV; j++) {
            int t = n * N_CONV + j;
            k_spmm<<<spmm_blocks, 256>>>((const float4*)dg_x, (float4*)dg_m,
                                         t > 0 ? 1 : 0);
            k_gemm128<<<gemm_blocks, 128, gemm_smem>>>(
                dg_m, conv_w + (size_t)j * HIDDEN * HIDDEN, dg_x, N_NODES, HIDDEN, 1,
                bn_gamma + j * HIDDEN, bn_beta + j * HIDDEN);
        }
        k_pool<<<(N_GRAPHS * 32 + 255) / 256, 256>>>((const float4*)dg_x, n);
    }

    k_mlp<<<N_GRAPHS, 128>>>(W1, b1, W2, b2, out);
}

// round 13
// speedup vs baseline: 1.0461x; 1.0461x over previous
#include <cuda_runtime.h>
#include <cuda_bf16.h>
#include <math.h>
#include <stdint.h>

// ---------------------------------------------------------------------------
// NgramRF GNN — R10 base (best measured 3038us) + launch-graph compression:
//  (a) k_pool fused into the following step's k_spmm as tail blocks
//  (b) k_pad + k_hist fused into one setup kernel
// Hot kernels (GEMM/SpMM) are byte-identical to R10.
// ---------------------------------------------------------------------------

#define N_NODES  100000
#define N_EDGES  1600000
#define N_GRAPHS 4096
#define IN_FEAT  74
#define PADK     96
#define HIDDEN   128
#define OUT_FEAT 128
#define N_CONV   3
#define NGRAM    6
#define BN_EPS   1e-5f

typedef unsigned long long u64;

#define SPMM_BLOCKS ((N_NODES * 32 + 255) / 256)
#define POOL_BLOCKS ((N_GRAPHS * 32 + 255) / 256)

// ------------------------- device scratch (static) -------------------------
__device__ float g_x[N_NODES * HIDDEN];     // pre-BN node features
__device__ float g_m[N_NODES * HIDDEN];     // aggregated messages
__device__ float g_featp[N_NODES * PADK];   // padded features
__device__ float g_Winp[PADK * HIDDEN];     // padded W_in
__device__ int   g_deg[N_NODES];
__device__ int   g_rowptr[N_NODES + 1];
__device__ int   g_cursor[N_NODES];
__device__ int   g_col[N_EDGES];
__device__ int   g_gdeg[N_GRAPHS];
__device__ int   g_growptr[N_GRAPHS + 1];
__device__ float g_combined[N_GRAPHS * HIDDEN];
__device__ float g_sum[HIDDEN];
__device__ float g_sumsq[HIDDEN];
__device__ float g_scale[HIDDEN];
__device__ float g_shift[HIDDEN];
__device__ float g_w[NGRAM];

// ------------------------------ helpers -------------------------------------
__device__ __forceinline__ u64 fma2(u64 a, u64 b, u64 c) {
    u64 d;
    asm("fma.rn.f32x2 %0, %1, %2, %3;" : "=l"(d) : "l"(a), "l"(b), "l"(c));
    return d;
}
__device__ __forceinline__ u64 dup2(float x) {
    u64 d;
    asm("mov.b64 %0, {%1, %1};" : "=l"(d) : "f"(x));
    return d;
}
__device__ __forceinline__ void unpack2(u64 v, float& lo, float& hi) {
    asm("mov.b64 {%0, %1}, %2;" : "=f"(lo), "=f"(hi) : "l"(v));
}
__device__ __forceinline__ uint32_t smem_u32(const void* p) {
    uint32_t a;
    asm("{ .reg .u64 t; cvta.to.shared.u64 t, %1; cvt.u32.u64 %0, t; }" : "=r"(a) : "l"(p));
    return a;
}
__device__ __forceinline__ void cp16(uint32_t dst, const void* src, int src_bytes) {
    asm volatile("cp.async.cg.shared.global [%0], [%1], 16, %2;"
                 :: "r"(dst), "l"(src), "r"(src_bytes));
}
#define CP_COMMIT()  asm volatile("cp.async.commit_group;" ::: "memory")
#define CP_WAIT(N)   asm volatile("cp.async.wait_group %0;" :: "n"(N) : "memory")

// ------------------------------ tiny kernels -------------------------------
__global__ void k_softmax(const float* __restrict__ ngw) {
    if (threadIdx.x == 0) {
        float mx = -1e30f;
        for (int i = 0; i < NGRAM; i++) mx = fmaxf(mx, ngw[i]);
        float e[NGRAM], s = 0.f;
        for (int i = 0; i < NGRAM; i++) { e[i] = expf(ngw[i] - mx); s += e[i]; }
        for (int i = 0; i < NGRAM; i++) g_w[i] = e[i] / s;
    }
}

// fused setup: pad features/W_in AND build dst histogram (independent work)
__global__ void __launch_bounds__(256)
k_padhist(const float* __restrict__ f, const float* __restrict__ Win,
          const int* __restrict__ dst) {
    int i  = blockIdx.x * blockDim.x + threadIdx.x;
    int st = gridDim.x * blockDim.x;
    const int totF = N_NODES * PADK;
    for (int j = i; j < totF; j += st) {
        int r = j / PADK;
        int c = j - r * PADK;
        g_featp[j] = (c < IN_FEAT) ? f[(size_t)r * IN_FEAT + c] : 0.f;
    }
    const int totW = PADK * HIDDEN;
    for (int j = i; j < totW; j += st) {
        int w = j >> 7;
        g_Winp[j] = (w < IN_FEAT) ? Win[j] : 0.f;
    }
    for (int e = i; e < N_EDGES; e += st) atomicAdd(&g_deg[dst[e]], 1);
}

__global__ void k_ghist(const int* __restrict__ gid) {
    int i  = blockIdx.x * blockDim.x + threadIdx.x;
    int st = gridDim.x * blockDim.x;
    for (int v = i; v < N_NODES; v += st) atomicAdd(&g_gdeg[gid[v]], 1);
}

__global__ void k_scan(const int* __restrict__ deg, int* __restrict__ rowptr,
                       int* __restrict__ cursor, int n) {
    __shared__ int ssum[1024];
    const int T = 1024;
    int t   = threadIdx.x;
    int per = (n + T - 1) / T;
    int lo  = t * per;
    int hi  = min(lo + per, n);
    int s = 0;
    for (int i = lo; i < hi; i++) s += deg[i];
    ssum[t] = s;
    __syncthreads();
    for (int off = 1; off < T; off <<= 1) {
        int v = (t >= off) ? ssum[t - off] : 0;
        __syncthreads();
        ssum[t] += v;
        __syncthreads();
    }
    int run = ssum[t] - s;
    for (int i = lo; i < hi; i++) {
        rowptr[i] = run;
        if (cursor) cursor[i] = run;
        run += deg[i];
    }
    if (t == T - 1) rowptr[n] = ssum[T - 1];
}

__global__ void k_fill(const int* __restrict__ src, const int* __restrict__ dst) {
    int i  = blockIdx.x * blockDim.x + threadIdx.x;
    int st = gridDim.x * blockDim.x;
    for (int e = i; e < N_EDGES; e += st) {
        int p = atomicAdd(&g_cursor[dst[e]], 1);
        g_col[p] = src[e];
    }
}

// ------------- pool body (device fn, used fused and standalone) -------------
__device__ __forceinline__ void pool_body(const float4* __restrict__ x4,
                                          int n, int gwarp, int lane) {
    if (gwarp >= N_GRAPHS) return;
    float4 sc = ((const float4*)g_scale)[lane];
    float4 sh = ((const float4*)g_shift)[lane];
    int v = g_growptr[gwarp], end = g_growptr[gwarp + 1];
    float4 a = make_float4(0.f, 0.f, 0.f, 0.f);
    for (; v < end; v++) {
        float4 t = __ldg(x4 + (size_t)v * 32 + lane);
        a.x += fmaxf(fmaf(t.x, sc.x, sh.x), 0.f);
        a.y += fmaxf(fmaf(t.y, sc.y, sh.y), 0.f);
        a.z += fmaxf(fmaf(t.z, sc.z, sh.z), 0.f);
        a.w += fmaxf(fmaf(t.w, sc.w, sh.w), 0.f);
    }
    float w = g_w[n];
    float4* cb = (float4*)g_combined;
    float4 c = cb[(size_t)gwarp * 32 + lane];
    c.x += w * a.x; c.y += w * a.y; c.z += w * a.z; c.w += w * a.w;
    cb[(size_t)gwarp * 32 + lane] = c;
}

// ------- SpMM: warp per row (R10 body) + optional fused pool tail blocks -----
__global__ void __launch_bounds__(256)
k_spmm(const float4* __restrict__ x4, float4* __restrict__ m4, int apply_bn,
       int pool_n) {
    int lane = threadIdx.x & 31;
    if (blockIdx.x >= SPMM_BLOCKS) {
        // pool tail (only present when pool_n >= 0)
        int gwarp = ((blockIdx.x - SPMM_BLOCKS) * 256 + (int)threadIdx.x) >> 5;
        pool_body(x4, pool_n, gwarp, lane);
        return;
    }
    int wid = (blockIdx.x * blockDim.x + threadIdx.x) >> 5;
    if (wid >= N_NODES) return;
    int e = __ldg(g_rowptr + wid), end = __ldg(g_rowptr + wid + 1);
    float4 a = make_float4(0.f, 0.f, 0.f, 0.f);
    if (apply_bn) {
        float4 sc = ((const float4*)g_scale)[lane];
        float4 sh = ((const float4*)g_shift)[lane];
        for (; e + 2 <= end; e += 2) {
            int s0 = __ldg(g_col + e + 0);
            int s1 = __ldg(g_col + e + 1);
            float4 v0 = __ldg(x4 + (size_t)s0 * 32 + lane);
            float4 v1 = __ldg(x4 + (size_t)s1 * 32 + lane);
            a.x += fmaxf(fmaf(v0.x, sc.x, sh.x), 0.f) + fmaxf(fmaf(v1.x, sc.x, sh.x), 0.f);
            a.y += fmaxf(fmaf(v0.y, sc.y, sh.y), 0.f) + fmaxf(fmaf(v1.y, sc.y, sh.y), 0.f);
            a.z += fmaxf(fmaf(v0.z, sc.z, sh.z), 0.f) + fmaxf(fmaf(v1.z, sc.z, sh.z), 0.f);
            a.w += fmaxf(fmaf(v0.w, sc.w, sh.w), 0.f) + fmaxf(fmaf(v1.w, sc.w, sh.w), 0.f);
        }
        for (; e < end; e++) {
            int s = __ldg(g_col + e);
            float4 v = __ldg(x4 + (size_t)s * 32 + lane);
            a.x += fmaxf(fmaf(v.x, sc.x, sh.x), 0.f);
            a.y += fmaxf(fmaf(v.y, sc.y, sh.y), 0.f);
            a.z += fmaxf(fmaf(v.z, sc.z, sh.z), 0.f);
            a.w += fmaxf(fmaf(v.w, sc.w, sh.w), 0.f);
        }
    } else {
        for (; e + 4 <= end; e += 4) {
            int s0 = __ldg(g_col + e + 0);
            int s1 = __ldg(g_col + e + 1);
            int s2 = __ldg(g_col + e + 2);
            int s3 = __ldg(g_col + e + 3);
            float4 v0 = __ldg(x4 + (size_t)s0 * 32 + lane);
            float4 v1 = __ldg(x4 + (size_t)s1 * 32 + lane);
            float4 v2 = __ldg(x4 + (size_t)s2 * 32 + lane);
            float4 v3 = __ldg(x4 + (size_t)s3 * 32 + lane);
            a.x += (v0.x + v1.x) + (v2.x + v3.x);
            a.y += (v0.y + v1.y) + (v2.y + v3.y);
            a.z += (v0.z + v1.z) + (v2.z + v3.z);
            a.w += (v0.w + v1.w) + (v2.w + v3.w);
        }
        for (; e < end; e++) {
            int s = __ldg(g_col + e);
            float4 v = __ldg(x4 + (size_t)s * 32 + lane);
            a.x += v.x; a.y += v.y; a.z += v.z; a.w += v.w;
        }
    }
    m4[(size_t)wid * 32 + lane] = a;
}

// standalone pool (last ngram only)
__global__ void __launch_bounds__(256)
k_pool(const float4* __restrict__ x4, int n) {
    int gwarp = (blockIdx.x * blockDim.x + threadIdx.x) >> 5;
    pool_body(x4, n, gwarp, threadIdx.x & 31);
}

// -- GEMM: C[n,128] = B[n,K] @ W[K,128], f32x2 8x8/thread, cp.async pipeline --
// (verbatim R10: natural regs, separate finalize kernel)
#define BM 64
#define BN 128
#define BK 32
#define ASTR 36
#define GEMM_SMEM_FLOATS (2 * BM * ASTR + 2 * BK * BN)
__global__ void __launch_bounds__(128)
k_gemm128(const float* __restrict__ B, const float* __restrict__ W,
          float* __restrict__ C, int nrows, int K, int do_stats) {
    extern __shared__ float sm[];
    __shared__ float s_cs[BN], s_cq[BN];
    int tid = threadIdx.x;
    int ty  = tid >> 4;
    int tx  = tid & 15;
    int row0 = blockIdx.x * BM;

    uint32_t sA0 = smem_u32(sm);                       // [2][BM][ASTR]
    uint32_t sW0 = sA0 + 2 * BM * ASTR * 4;            // [2][BK][BN]
    const float* sA = sm;
    const float* sW = sm + 2 * BM * ASTR;

    const int nch = K / BK;

    auto issue = [&](int s, int b) {
#pragma unroll
        for (int q = 0; q < 4; q++) {
            int fi = tid + q * 128;
            int m  = fi >> 3;
            int k4 = fi & 7;
            int r  = row0 + m;
            int rc = min(r, nrows - 1);
            const float* src = B + (size_t)rc * K + s * BK + k4 * 4;
            int sb = (r < nrows) ? 16 : 0;
            cp16(sA0 + (((b * BM + m) * ASTR) + k4 * 4) * 4, src, sb);
        }
#pragma unroll
        for (int q = 0; q < 8; q++) {
            int fi = tid + q * 128;
            int kk = fi >> 5;
            int n4 = fi & 31;
            cp16(sW0 + (((b * BK + kk) * BN) + n4 * 4) * 4,
                 W + (size_t)(s * BK + kk) * BN + n4 * 4, 16);
        }
        CP_COMMIT();
    };

    u64 acc2[8][4];
#pragma unroll
    for (int i = 0; i < 8; i++)
#pragma unroll
        for (int j = 0; j < 4; j++) acc2[i][j] = 0ull;

    issue(0, 0);

    for (int s = 0; s < nch; s++) {
        int b = s & 1;
        if (s + 1 < nch) {
            issue(s + 1, b ^ 1);
            CP_WAIT(1);
        } else {
            CP_WAIT(0);
        }
        __syncthreads();
        const float* cA = sA + b * BM * ASTR;
        const float* cW = sW + b * BK * BN;
#pragma unroll
        for (int kk = 0; kk < BK; kk++) {
            const u64* pW = (const u64*)(cW + kk * BN + tx * 8);
            u64 w0 = pW[0], w1 = pW[1], w2 = pW[2], w3 = pW[3];
#pragma unroll
            for (int i = 0; i < 8; i++) {
                u64 a2 = dup2(cA[(ty * 8 + i) * ASTR + kk]);
                acc2[i][0] = fma2(a2, w0, acc2[i][0]);
                acc2[i][1] = fma2(a2, w1, acc2[i][1]);
                acc2[i][2] = fma2(a2, w2, acc2[i][2]);
                acc2[i][3] = fma2(a2, w3, acc2[i][3]);
            }
        }
        __syncthreads();
    }

    float a[8][8];
#pragma unroll
    for (int i = 0; i < 8; i++)
#pragma unroll
        for (int j = 0; j < 4; j++) unpack2(acc2[i][j], a[i][2 * j], a[i][2 * j + 1]);

    if (do_stats) {
        s_cs[tid] = 0.f;
        s_cq[tid] = 0.f;
    }
    __syncthreads();
    if (do_stats) {
#pragma unroll
        for (int j = 0; j < 8; j++) {
            float cs = 0.f, cq = 0.f;
#pragma unroll
            for (int i = 0; i < 8; i++) { float v = a[i][j]; cs += v; cq += v * v; }
            atomicAdd(&s_cs[tx * 8 + j], cs);
            atomicAdd(&s_cq[tx * 8 + j], cq);
        }
        __syncthreads();
        atomicAdd(&g_sum[tid],   s_cs[tid]);
        atomicAdd(&g_sumsq[tid], s_cq[tid]);
    }

#pragma unroll
    for (int i = 0; i < 8; i++) {
        int r = row0 + ty * 8 + i;
        if (r < nrows) {
            float4* o = (float4*)(C + (size_t)r * BN + tx * 8);
            o[0] = make_float4(a[i][0], a[i][1], a[i][2], a[i][3]);
            o[1] = make_float4(a[i][4], a[i][5], a[i][6], a[i][7]);
        }
    }
}

__global__ void k_finalize(const float* __restrict__ gamma, const float* __restrict__ beta) {
    int c = threadIdx.x;
    if (c < HIDDEN) {
        float invN = 1.f / (float)N_NODES;
        float mean = g_sum[c] * invN;
        float var  = g_sumsq[c] * invN - mean * mean;
        float sc   = gamma[c] * rsqrtf(var + BN_EPS);
        g_scale[c] = sc;
        g_shift[c] = beta[c] - mean * sc;
        g_sum[c] = 0.f;
        g_sumsq[c] = 0.f;
    }
}

// ---------------------- MLP head: block per graph ---------------------------
__global__ void __launch_bounds__(128)
k_mlp(const float* __restrict__ W1, const float* __restrict__ b1,
      const float* __restrict__ W2, const float* __restrict__ b2,
      float* __restrict__ out) {
    int g = blockIdx.x;
    int t = threadIdx.x;
    __shared__ float row[HIDDEN];
    __shared__ float red[128];
    row[t] = g_combined[(size_t)g * HIDDEN + t];
    __syncthreads();
    float acc = b1[t];
#pragma unroll 8
    for (int k = 0; k < HIDDEN; k++) acc = fmaf(row[k], W1[(size_t)k * OUT_FEAT + t], acc);
    acc = (acc > 0.f) ? acc : 0.01f * acc;
    red[t] = acc * W2[t];
    __syncthreads();
    for (int off = 64; off > 0; off >>= 1) {
        if (t < off) red[t] += red[t + off];
        __syncthreads();
    }
    if (t == 0) {
        float z = red[0] + b2[0];
        out[g] = 1.f / (1.f + expf(-z));
    }
}

// ------------------------------- launcher -----------------------------------
extern "C" void kernel_launch(void* const* d_in, const int* in_sizes, int n_in,
                              void* d_out, int out_size) {
    const float* features = (const float*)d_in[0];
    const float* W_in     = (const float*)d_in[1];
    const float* conv_w   = (const float*)d_in[2];
    const float* bn_gamma = (const float*)d_in[3];
    const float* bn_beta  = (const float*)d_in[4];
    const float* ngw      = (const float*)d_in[5];
    const float* W1       = (const float*)d_in[6];
    const float* b1       = (const float*)d_in[7];
    const float* W2       = (const float*)d_in[8];
    const float* b2       = (const float*)d_in[9];
    const int*   src      = (const int*)d_in[10];
    const int*   dst      = (const int*)d_in[11];
    const int*   gid      = (const int*)d_in[12];
    float* out = (float*)d_out;

    float *dg_x, *dg_m, *dg_featp, *dg_Winp, *dg_comb, *dg_sum, *dg_sumsq;
    int *dg_deg, *dg_rowptr, *dg_cursor, *dg_gdeg, *dg_growptr;
    cudaGetSymbolAddress((void**)&dg_x, g_x);
    cudaGetSymbolAddress((void**)&dg_m, g_m);
    cudaGetSymbolAddress((void**)&dg_featp, g_featp);
    cudaGetSymbolAddress((void**)&dg_Winp, g_Winp);
    cudaGetSymbolAddress((void**)&dg_comb, g_combined);
    cudaGetSymbolAddress((void**)&dg_sum, g_sum);
    cudaGetSymbolAddress((void**)&dg_sumsq, g_sumsq);
    cudaGetSymbolAddress((void**)&dg_deg, g_deg);
    cudaGetSymbolAddress((void**)&dg_rowptr, g_rowptr);
    cudaGetSymbolAddress((void**)&dg_cursor, g_cursor);
    cudaGetSymbolAddress((void**)&dg_gdeg, g_gdeg);
    cudaGetSymbolAddress((void**)&dg_growptr, g_growptr);

    cudaFuncSetAttribute(k_gemm128, cudaFuncAttributeMaxDynamicSharedMemorySize,
                         GEMM_SMEM_FLOATS * sizeof(float));

    // zero scratch via memset nodes
    cudaMemsetAsync(dg_deg, 0, N_NODES * sizeof(int));
    cudaMemsetAsync(dg_gdeg, 0, N_GRAPHS * sizeof(int));
    cudaMemsetAsync(dg_comb, 0, N_GRAPHS * HIDDEN * sizeof(float));
    cudaMemsetAsync(dg_sum, 0, HIDDEN * sizeof(float));
    cudaMemsetAsync(dg_sumsq, 0, HIDDEN * sizeof(float));

    const int gemm_blocks = (N_NODES + BM - 1) / BM;
    const size_t gemm_smem = GEMM_SMEM_FLOATS * sizeof(float);

    // launch #4 (profiled) = pipelined GEMM (vec path, K=96), natural regs
    k_padhist<<<2048, 256>>>(features, W_in, dst);                       // 1
    k_scan<<<1, 1024>>>(dg_deg, dg_rowptr, dg_cursor, N_NODES);          // 2
    k_fill<<<2048, 256>>>(src, dst);                                     // 3
    k_gemm128<<<gemm_blocks, 128, gemm_smem>>>(dg_featp, dg_Winp, dg_x,  // 4
                                               N_NODES, PADK, 0);
    k_ghist<<<256, 256>>>(gid);
    k_scan<<<1, 1024>>>(dg_gdeg, dg_growptr, (int*)0, N_GRAPHS);
    k_softmax<<<1, 32>>>(ngw);

    for (int n = 0; n < NGRAM; n++) {
        for (int j = 0; j < N_CONV; j++) {
            int t = n * N_CONV + j;
            // fuse pool of previous ngram into this spmm's tail blocks
            int pool_n = (j == 0 && n > 0) ? (n - 1) : -1;
            int grid = SPMM_BLOCKS + (pool_n >= 0 ? POOL_BLOCKS : 0);
            k_spmm<<<grid, 256>>>((const float4*)dg_x, (float4*)dg_m,
                                  t > 0 ? 1 : 0, pool_n);
            k_gemm128<<<gemm_blocks, 128, gemm_smem>>>(
                dg_m, conv_w + (size_t)j * HIDDEN * HIDDEN, dg_x, N_NODES, HIDDEN, 1);
            k_finalize<<<1, 128>>>(bn_gamma + j * HIDDEN, bn_beta + j * HIDDEN);
        }
    }
    // last ngram's pool (no following spmm)
    k_pool<<<POOL_BLOCKS, 256>>>((const float4*)dg_x, NGRAM - 1);

    k_mlp<<<N_GRAPHS, 128>>>(W1, b1, W2, b2, out);
}

// round 14
// speedup vs baseline: 1.0473x; 1.0011x over previous
#include <cuda_runtime.h>
#include <cuda_bf16.h>
#include <math.h>
#include <stdint.h>

// ---------------------------------------------------------------------------
// NgramRF GNN — R13 base (2973us) + persistent-CTA GEMM whose cp.async
// double-buffer pipeline spans tile boundaries (epilogue overlaps prefetch).
// ---------------------------------------------------------------------------

#define N_NODES  100000
#define N_EDGES  1600000
#define N_GRAPHS 4096
#define IN_FEAT  74
#define PADK     96
#define HIDDEN   128
#define OUT_FEAT 128
#define N_CONV   3
#define NGRAM    6
#define BN_EPS   1e-5f

typedef unsigned long long u64;

#define SPMM_BLOCKS ((N_NODES * 32 + 255) / 256)
#define POOL_BLOCKS ((N_GRAPHS * 32 + 255) / 256)
#define GEMM_GRID   444                      // 148 SM x 3 resident blocks

// ------------------------- device scratch (static) -------------------------
__device__ float g_x[N_NODES * HIDDEN];
__device__ float g_m[N_NODES * HIDDEN];
__device__ float g_featp[N_NODES * PADK];
__device__ float g_Winp[PADK * HIDDEN];
__device__ int   g_deg[N_NODES];
__device__ int   g_rowptr[N_NODES + 1];
__device__ int   g_cursor[N_NODES];
__device__ int   g_col[N_EDGES];
__device__ int   g_gdeg[N_GRAPHS];
__device__ int   g_growptr[N_GRAPHS + 1];
__device__ float g_combined[N_GRAPHS * HIDDEN];
__device__ float g_sum[HIDDEN];
__device__ float g_sumsq[HIDDEN];
__device__ float g_scale[HIDDEN];
__device__ float g_shift[HIDDEN];
__device__ float g_w[NGRAM];

// ------------------------------ helpers -------------------------------------
__device__ __forceinline__ u64 fma2(u64 a, u64 b, u64 c) {
    u64 d;
    asm("fma.rn.f32x2 %0, %1, %2, %3;" : "=l"(d) : "l"(a), "l"(b), "l"(c));
    return d;
}
__device__ __forceinline__ u64 dup2(float x) {
    u64 d;
    asm("mov.b64 %0, {%1, %1};" : "=l"(d) : "f"(x));
    return d;
}
__device__ __forceinline__ void unpack2(u64 v, float& lo, float& hi) {
    asm("mov.b64 {%0, %1}, %2;" : "=f"(lo), "=f"(hi) : "l"(v));
}
__device__ __forceinline__ uint32_t smem_u32(const void* p) {
    uint32_t a;
    asm("{ .reg .u64 t; cvta.to.shared.u64 t, %1; cvt.u32.u64 %0, t; }" : "=r"(a) : "l"(p));
    return a;
}
__device__ __forceinline__ void cp16(uint32_t dst, const void* src, int src_bytes) {
    asm volatile("cp.async.cg.shared.global [%0], [%1], 16, %2;"
                 :: "r"(dst), "l"(src), "r"(src_bytes));
}
#define CP_COMMIT()  asm volatile("cp.async.commit_group;" ::: "memory")
#define CP_WAIT(N)   asm volatile("cp.async.wait_group %0;" :: "n"(N) : "memory")

// ------------------------------ tiny kernels -------------------------------
__global__ void k_softmax(const float* __restrict__ ngw) {
    if (threadIdx.x == 0) {
        float mx = -1e30f;
        for (int i = 0; i < NGRAM; i++) mx = fmaxf(mx, ngw[i]);
        float e[NGRAM], s = 0.f;
        for (int i = 0; i < NGRAM; i++) { e[i] = expf(ngw[i] - mx); s += e[i]; }
        for (int i = 0; i < NGRAM; i++) g_w[i] = e[i] / s;
    }
}

__global__ void __launch_bounds__(256)
k_padhist(const float* __restrict__ f, const float* __restrict__ Win,
          const int* __restrict__ dst) {
    int i  = blockIdx.x * blockDim.x + threadIdx.x;
    int st = gridDim.x * blockDim.x;
    const int totF = N_NODES * PADK;
    for (int j = i; j < totF; j += st) {
        int r = j / PADK;
        int c = j - r * PADK;
        g_featp[j] = (c < IN_FEAT) ? f[(size_t)r * IN_FEAT + c] : 0.f;
    }
    const int totW = PADK * HIDDEN;
    for (int j = i; j < totW; j += st) {
        int w = j >> 7;
        g_Winp[j] = (w < IN_FEAT) ? Win[j] : 0.f;
    }
    for (int e = i; e < N_EDGES; e += st) atomicAdd(&g_deg[dst[e]], 1);
}

__global__ void k_ghist(const int* __restrict__ gid) {
    int i  = blockIdx.x * blockDim.x + threadIdx.x;
    int st = gridDim.x * blockDim.x;
    for (int v = i; v < N_NODES; v += st) atomicAdd(&g_gdeg[gid[v]], 1);
}

__global__ void k_scan(const int* __restrict__ deg, int* __restrict__ rowptr,
                       int* __restrict__ cursor, int n) {
    __shared__ int ssum[1024];
    const int T = 1024;
    int t   = threadIdx.x;
    int per = (n + T - 1) / T;
    int lo  = t * per;
    int hi  = min(lo + per, n);
    int s = 0;
    for (int i = lo; i < hi; i++) s += deg[i];
    ssum[t] = s;
    __syncthreads();
    for (int off = 1; off < T; off <<= 1) {
        int v = (t >= off) ? ssum[t - off] : 0;
        __syncthreads();
        ssum[t] += v;
        __syncthreads();
    }
    int run = ssum[t] - s;
    for (int i = lo; i < hi; i++) {
        rowptr[i] = run;
        if (cursor) cursor[i] = run;
        run += deg[i];
    }
    if (t == T - 1) rowptr[n] = ssum[T - 1];
}

__global__ void k_fill(const int* __restrict__ src, const int* __restrict__ dst) {
    int i  = blockIdx.x * blockDim.x + threadIdx.x;
    int st = gridDim.x * blockDim.x;
    for (int e = i; e < N_EDGES; e += st) {
        int p = atomicAdd(&g_cursor[dst[e]], 1);
        g_col[p] = src[e];
    }
}

// ------------- pool body (device fn, used fused and standalone) -------------
__device__ __forceinline__ void pool_body(const float4* __restrict__ x4,
                                          int n, int gwarp, int lane) {
    if (gwarp >= N_GRAPHS) return;
    float4 sc = ((const float4*)g_scale)[lane];
    float4 sh = ((const float4*)g_shift)[lane];
    int v = g_growptr[gwarp], end = g_growptr[gwarp + 1];
    float4 a = make_float4(0.f, 0.f, 0.f, 0.f);
    for (; v < end; v++) {
        float4 t = __ldg(x4 + (size_t)v * 32 + lane);
        a.x += fmaxf(fmaf(t.x, sc.x, sh.x), 0.f);
        a.y += fmaxf(fmaf(t.y, sc.y, sh.y), 0.f);
        a.z += fmaxf(fmaf(t.z, sc.z, sh.z), 0.f);
        a.w += fmaxf(fmaf(t.w, sc.w, sh.w), 0.f);
    }
    float w = g_w[n];
    float4* cb = (float4*)g_combined;
    float4 c = cb[(size_t)gwarp * 32 + lane];
    c.x += w * a.x; c.y += w * a.y; c.z += w * a.z; c.w += w * a.w;
    cb[(size_t)gwarp * 32 + lane] = c;
}

// ------- SpMM: warp per row + optional fused pool tail blocks ----------------
__global__ void __launch_bounds__(256)
k_spmm(const float4* __restrict__ x4, float4* __restrict__ m4, int apply_bn,
       int pool_n) {
    int lane = threadIdx.x & 31;
    if (blockIdx.x >= SPMM_BLOCKS) {
        int gwarp = ((blockIdx.x - SPMM_BLOCKS) * 256 + (int)threadIdx.x) >> 5;
        pool_body(x4, pool_n, gwarp, lane);
        return;
    }
    int wid = (blockIdx.x * blockDim.x + threadIdx.x) >> 5;
    if (wid >= N_NODES) return;
    int e = __ldg(g_rowptr + wid), end = __ldg(g_rowptr + wid + 1);
    float4 a = make_float4(0.f, 0.f, 0.f, 0.f);
    if (apply_bn) {
        float4 sc = ((const float4*)g_scale)[lane];
        float4 sh = ((const float4*)g_shift)[lane];
        for (; e + 2 <= end; e += 2) {
            int s0 = __ldg(g_col + e + 0);
            int s1 = __ldg(g_col + e + 1);
            float4 v0 = __ldg(x4 + (size_t)s0 * 32 + lane);
            float4 v1 = __ldg(x4 + (size_t)s1 * 32 + lane);
            a.x += fmaxf(fmaf(v0.x, sc.x, sh.x), 0.f) + fmaxf(fmaf(v1.x, sc.x, sh.x), 0.f);
            a.y += fmaxf(fmaf(v0.y, sc.y, sh.y), 0.f) + fmaxf(fmaf(v1.y, sc.y, sh.y), 0.f);
            a.z += fmaxf(fmaf(v0.z, sc.z, sh.z), 0.f) + fmaxf(fmaf(v1.z, sc.z, sh.z), 0.f);
            a.w += fmaxf(fmaf(v0.w, sc.w, sh.w), 0.f) + fmaxf(fmaf(v1.w, sc.w, sh.w), 0.f);
        }
        for (; e < end; e++) {
            int s = __ldg(g_col + e);
            float4 v = __ldg(x4 + (size_t)s * 32 + lane);
            a.x += fmaxf(fmaf(v.x, sc.x, sh.x), 0.f);
            a.y += fmaxf(fmaf(v.y, sc.y, sh.y), 0.f);
            a.z += fmaxf(fmaf(v.z, sc.z, sh.z), 0.f);
            a.w += fmaxf(fmaf(v.w, sc.w, sh.w), 0.f);
        }
    } else {
        for (; e + 4 <= end; e += 4) {
            int s0 = __ldg(g_col + e + 0);
            int s1 = __ldg(g_col + e + 1);
            int s2 = __ldg(g_col + e + 2);
            int s3 = __ldg(g_col + e + 3);
            float4 v0 = __ldg(x4 + (size_t)s0 * 32 + lane);
            float4 v1 = __ldg(x4 + (size_t)s1 * 32 + lane);
            float4 v2 = __ldg(x4 + (size_t)s2 * 32 + lane);
            float4 v3 = __ldg(x4 + (size_t)s3 * 32 + lane);
            a.x += (v0.x + v1.x) + (v2.x + v3.x);
            a.y += (v0.y + v1.y) + (v2.y + v3.y);
            a.z += (v0.z + v1.z) + (v2.z + v3.z);
            a.w += (v0.w + v1.w) + (v2.w + v3.w);
        }
        for (; e < end; e++) {
            int s = __ldg(g_col + e);
            float4 v = __ldg(x4 + (size_t)s * 32 + lane);
            a.x += v.x; a.y += v.y; a.z += v.z; a.w += v.w;
        }
    }
    m4[(size_t)wid * 32 + lane] = a;
}

__global__ void __launch_bounds__(256)
k_pool(const float4* __restrict__ x4, int n) {
    int gwarp = (blockIdx.x * blockDim.x + threadIdx.x) >> 5;
    pool_body(x4, n, gwarp, threadIdx.x & 31);
}

// -- GEMM: persistent CTAs, f32x2 8x8/thread, cross-tile cp.async pipeline ----
#define BM 64
#define BN 128
#define BK 32
#define ASTR 36
#define GEMM_SMEM_FLOATS (2 * BM * ASTR + 2 * BK * BN)
__global__ void __launch_bounds__(128)
k_gemm128(const float* __restrict__ B, const float* __restrict__ W,
          float* __restrict__ C, int nrows, int K, int do_stats) {
    extern __shared__ float sm[];
    __shared__ float s_cs[BN], s_cq[BN];
    int tid = threadIdx.x;
    int ty  = tid >> 4;
    int tx  = tid & 15;

    uint32_t sA0 = smem_u32(sm);                       // [2][BM][ASTR]
    uint32_t sW0 = sA0 + 2 * BM * ASTR * 4;            // [2][BK][BN]
    const float* sA = sm;
    const float* sW = sm + 2 * BM * ASTR;

    const int nch    = K / BK;
    const int ntiles = (nrows + BM - 1) / BM;

    auto issue = [&](int tile, int s, int b) {
        int row0 = tile * BM;
#pragma unroll
        for (int q = 0; q < 4; q++) {
            int fi = tid + q * 128;
            int m  = fi >> 3;
            int k4 = fi & 7;
            int r  = row0 + m;
            int rc = min(r, nrows - 1);
            const float* src = B + (size_t)rc * K + s * BK + k4 * 4;
            int sb = (r < nrows) ? 16 : 0;
            cp16(sA0 + (((b * BM + m) * ASTR) + k4 * 4) * 4, src, sb);
        }
#pragma unroll
        for (int q = 0; q < 8; q++) {
            int fi = tid + q * 128;
            int kk = fi >> 5;
            int n4 = fi & 31;
            cp16(sW0 + (((b * BK + kk) * BN) + n4 * 4) * 4,
                 W + (size_t)(s * BK + kk) * BN + n4 * 4, 16);
        }
        CP_COMMIT();
    };

    int pb = 0;
    if ((int)blockIdx.x < ntiles) issue(blockIdx.x, 0, 0);

    for (int tile = blockIdx.x; tile < ntiles; tile += gridDim.x) {
        int row0 = tile * BM;
        u64 acc2[8][4];
#pragma unroll
        for (int i = 0; i < 8; i++)
#pragma unroll
            for (int j = 0; j < 4; j++) acc2[i][j] = 0ull;

        for (int s = 0; s < nch; s++) {
            bool next_chunk = (s + 1 < nch);
            int  ntile      = tile + gridDim.x;
            bool next_tile  = (!next_chunk) && (ntile < ntiles);
            if (next_chunk || next_tile) {
                if (next_chunk) issue(tile, s + 1, pb ^ 1);
                else            issue(ntile, 0, pb ^ 1);
                CP_WAIT(1);
            } else {
                CP_WAIT(0);
            }
            __syncthreads();
            const float* cA = sA + pb * BM * ASTR;
            const float* cW = sW + pb * BK * BN;
#pragma unroll
            for (int kk = 0; kk < BK; kk++) {
                const u64* pW = (const u64*)(cW + kk * BN + tx * 8);
                u64 w0 = pW[0], w1 = pW[1], w2 = pW[2], w3 = pW[3];
#pragma unroll
                for (int i = 0; i < 8; i++) {
                    u64 a2 = dup2(cA[(ty * 8 + i) * ASTR + kk]);
                    acc2[i][0] = fma2(a2, w0, acc2[i][0]);
                    acc2[i][1] = fma2(a2, w1, acc2[i][1]);
                    acc2[i][2] = fma2(a2, w2, acc2[i][2]);
                    acc2[i][3] = fma2(a2, w3, acc2[i][3]);
                }
            }
            __syncthreads();
            pb ^= 1;
        }

        // ---- epilogue (overlaps the in-flight prefetch of the next tile) ----
        float a[8][8];
#pragma unroll
        for (int i = 0; i < 8; i++)
#pragma unroll
            for (int j = 0; j < 4; j++) unpack2(acc2[i][j], a[i][2 * j], a[i][2 * j + 1]);

        if (do_stats) {
            s_cs[tid] = 0.f;
            s_cq[tid] = 0.f;
            __syncthreads();
#pragma unroll
            for (int j = 0; j < 8; j++) {
                float cs = 0.f, cq = 0.f;
#pragma unroll
                for (int i = 0; i < 8; i++) { float v = a[i][j]; cs += v; cq += v * v; }
                atomicAdd(&s_cs[tx * 8 + j], cs);
                atomicAdd(&s_cq[tx * 8 + j], cq);
            }
            __syncthreads();
            atomicAdd(&g_sum[tid],   s_cs[tid]);
            atomicAdd(&g_sumsq[tid], s_cq[tid]);
        }

#pragma unroll
        for (int i = 0; i < 8; i++) {
            int r = row0 + ty * 8 + i;
            if (r < nrows) {
                float4* o = (float4*)(C + (size_t)r * BN + tx * 8);
                o[0] = make_float4(a[i][0], a[i][1], a[i][2], a[i][3]);
                o[1] = make_float4(a[i][4], a[i][5], a[i][6], a[i][7]);
            }
        }
    }
}

__global__ void k_finalize(const float* __restrict__ gamma, const float* __restrict__ beta) {
    int c = threadIdx.x;
    if (c < HIDDEN) {
        float invN = 1.f / (float)N_NODES;
        float mean = g_sum[c] * invN;
        float var  = g_sumsq[c] * invN - mean * mean;
        float sc   = gamma[c] * rsqrtf(var + BN_EPS);
        g_scale[c] = sc;
        g_shift[c] = beta[c] - mean * sc;
        g_sum[c] = 0.f;
        g_sumsq[c] = 0.f;
    }
}

// ---------------------- MLP head: block per graph ---------------------------
__global__ void __launch_bounds__(128)
k_mlp(const float* __restrict__ W1, const float* __restrict__ b1,
      const float* __restrict__ W2, const float* __restrict__ b2,
      float* __restrict__ out) {
    int g = blockIdx.x;
    int t = threadIdx.x;
    __shared__ float row[HIDDEN];
    __shared__ float red[128];
    row[t] = g_combined[(size_t)g * HIDDEN + t];
    __syncthreads();
    float acc = b1[t];
#pragma unroll 8
    for (int k = 0; k < HIDDEN; k++) acc = fmaf(row[k], W1[(size_t)k * OUT_FEAT + t], acc);
    acc = (acc > 0.f) ? acc : 0.01f * acc;
    red[t] = acc * W2[t];
    __syncthreads();
    for (int off = 64; off > 0; off >>= 1) {
        if (t < off) red[t] += red[t + off];
        __syncthreads();
    }
    if (t == 0) {
        float z = red[0] + b2[0];
        out[g] = 1.f / (1.f + expf(-z));
    }
}

// ------------------------------- launcher -----------------------------------
extern "C" void kernel_launch(void* const* d_in, const int* in_sizes, int n_in,
                              void* d_out, int out_size) {
    const float* features = (const float*)d_in[0];
    const float* W_in     = (const float*)d_in[1];
    const float* conv_w   = (const float*)d_in[2];
    const float* bn_gamma = (const float*)d_in[3];
    const float* bn_beta  = (const float*)d_in[4];
    const float* ngw      = (const float*)d_in[5];
    const float* W1       = (const float*)d_in[6];
    const float* b1       = (const float*)d_in[7];
    const float* W2       = (const float*)d_in[8];
    const float* b2       = (const float*)d_in[9];
    const int*   src      = (const int*)d_in[10];
    const int*   dst      = (const int*)d_in[11];
    const int*   gid      = (const int*)d_in[12];
    float* out = (float*)d_out;

    float *dg_x, *dg_m, *dg_featp, *dg_Winp, *dg_comb, *dg_sum, *dg_sumsq;
    int *dg_deg, *dg_rowptr, *dg_cursor, *dg_gdeg, *dg_growptr;
    cudaGetSymbolAddress((void**)&dg_x, g_x);
    cudaGetSymbolAddress((void**)&dg_m, g_m);
    cudaGetSymbolAddress((void**)&dg_featp, g_featp);
    cudaGetSymbolAddress((void**)&dg_Winp, g_Winp);
    cudaGetSymbolAddress((void**)&dg_comb, g_combined);
    cudaGetSymbolAddress((void**)&dg_sum, g_sum);
    cudaGetSymbolAddress((void**)&dg_sumsq, g_sumsq);
    cudaGetSymbolAddress((void**)&dg_deg, g_deg);
    cudaGetSymbolAddress((void**)&dg_rowptr, g_rowptr);
    cudaGetSymbolAddress((void**)&dg_cursor, g_cursor);
    cudaGetSymbolAddress((void**)&dg_gdeg, g_gdeg);
    cudaGetSymbolAddress((void**)&dg_growptr, g_growptr);

    cudaFuncSetAttribute(k_gemm128, cudaFuncAttributeMaxDynamicSharedMemorySize,
                         GEMM_SMEM_FLOATS * sizeof(float));

    // zero scratch via memset nodes
    cudaMemsetAsync(dg_deg, 0, N_NODES * sizeof(int));
    cudaMemsetAsync(dg_gdeg, 0, N_GRAPHS * sizeof(int));
    cudaMemsetAsync(dg_comb, 0, N_GRAPHS * HIDDEN * sizeof(float));
    cudaMemsetAsync(dg_sum, 0, HIDDEN * sizeof(float));
    cudaMemsetAsync(dg_sumsq, 0, HIDDEN * sizeof(float));

    const size_t gemm_smem = GEMM_SMEM_FLOATS * sizeof(float);

    // launch #4 (profiled) = persistent GEMM (vec path, K=96)
    k_padhist<<<2048, 256>>>(features, W_in, dst);                       // 1
    k_scan<<<1, 1024>>>(dg_deg, dg_rowptr, dg_cursor, N_NODES);          // 2
    k_fill<<<2048, 256>>>(src, dst);                                     // 3
    k_gemm128<<<GEMM_GRID, 128, gemm_smem>>>(dg_featp, dg_Winp, dg_x,    // 4
                                             N_NODES, PADK, 0);
    k_ghist<<<256, 256>>>(gid);
    k_scan<<<1, 1024>>>(dg_gdeg, dg_growptr, (int*)0, N_GRAPHS);
    k_softmax<<<1, 32>>>(ngw);

    for (int n = 0; n < NGRAM; n++) {
        for (int j = 0; j < N_CONV; j++) {
            int t = n * N_CONV + j;
            int pool_n = (j == 0 && n > 0) ? (n - 1) : -1;
            int grid = SPMM_BLOCKS + (pool_n >= 0 ? POOL_BLOCKS : 0);
            k_spmm<<<grid, 256>>>((const float4*)dg_x, (float4*)dg_m,
                                  t > 0 ? 1 : 0, pool_n);
            k_gemm128<<<GEMM_GRID, 128, gemm_smem>>>(
                dg_m, conv_w + (size_t)j * HIDDEN * HIDDEN, dg_x, N_NODES, HIDDEN, 1);
            k_finalize<<<1, 128>>>(bn_gamma + j * HIDDEN, bn_beta + j * HIDDEN);
        }
    }
    k_pool<<<POOL_BLOCKS, 256>>>((const float4*)dg_x, NGRAM - 1);

    k_mlp<<<N_GRAPHS, 128>>>(W1, b1, W2, b2, out);
}